// round 16
// baseline (speedup 1.0000x reference)
#include <cuda_runtime.h>
#include <cuda_bf16.h>
#include <math.h>

// Problem constants: B=4, T=2048, C=1024, H=16, D=64
#define BB 4
#define TT 2048
#define CC 1024
#define HH 16
#define DD 64
#define MM (BB*TT)        // 8192
#define C3 (3*CC)         // 3072

// q pre-scale: 1/sqrt(64) * log2(e)  (exp2-based softmax)
#define QSC (0.125f * 1.44269504088896340736f)

// ------------------------------------------------------------------
// Scratch (layouts as R15)
// ------------------------------------------------------------------
__device__ float g_q[(size_t)MM*CC];
__device__ float g_k[(size_t)MM*CC];
__device__ float g_v[(size_t)MM*CC];
__device__ float g_y[(size_t)MM*CC];
__device__ float g_xt[(size_t)MM*CC];
__device__ float g_wq[(size_t)CC*C3];
__device__ float g_wp[(size_t)CC*CC];
__device__ float g_cos[TT*32];
__device__ float g_sin[TT*32];

// ------------------------------------------------------------------
// helpers
// ------------------------------------------------------------------
__device__ __forceinline__ float f2tf32(float x) {
    unsigned r;
    asm("cvt.rna.tf32.f32 %0, %1;" : "=r"(r) : "f"(x));
    return __uint_as_float(r);
}

__device__ __forceinline__ float ex2(float x) {
    float r;
    asm("ex2.approx.f32 %0, %1;" : "=f"(r) : "f"(x));
    return r;
}

__device__ __forceinline__ void mma_tf32(float* c,
    unsigned a0, unsigned a1, unsigned a2, unsigned a3,
    unsigned b0, unsigned b1)
{
    asm volatile(
        "mma.sync.aligned.m16n8k8.row.col.f32.tf32.tf32.f32 "
        "{%0,%1,%2,%3}, {%4,%5,%6,%7}, {%8,%9}, {%0,%1,%2,%3};"
        : "+f"(c[0]), "+f"(c[1]), "+f"(c[2]), "+f"(c[3])
        : "r"(a0), "r"(a1), "r"(a2), "r"(a3), "r"(b0), "r"(b1));
}

__device__ __forceinline__ void cp16(unsigned dst, const void* src) {
    asm volatile("cp.async.cg.shared.global [%0], [%1], 16;" :: "r"(dst), "l"(src));
}
#define CP_COMMIT() asm volatile("cp.async.commit_group;")
#define CP_WAIT(N)  asm volatile("cp.async.wait_group %0;" :: "n"(N))

__device__ __forceinline__ unsigned smem_u32(const void* p) {
    return (unsigned)__cvta_generic_to_shared(p);
}

__device__ __forceinline__ int p8(int j) {
    return (j < 4) ? (j << 1) : (((j - 4) << 1) | 1);
}

// ------------------------------------------------------------------
// Prep (unchanged)
// ------------------------------------------------------------------
#define NB_X   4096
#define NB_WQT 3072
#define NB_WPT 1024
#define NB_TBL 256
#define NB_PREP (NB_X + NB_WQT + NB_WPT + NB_TBL)

__global__ __launch_bounds__(256) void prep_kernel(
    const float* __restrict__ x, const float* __restrict__ wq,
    const float* __restrict__ wp)
{
    const int blk = blockIdx.x;
    const int tid = threadIdx.x;

    if (blk < NB_X) {
        const size_t base = ((size_t)blk * 256 + tid) * 8;
        float in[8];
        *(float4*)&in[0] = *(const float4*)(x + base);
        *(float4*)&in[4] = *(const float4*)(x + base + 4);
        *(float4*)(g_xt + base) =
            make_float4(f2tf32(in[0]), f2tf32(in[4]), f2tf32(in[1]), f2tf32(in[5]));
        *(float4*)(g_xt + base + 4) =
            make_float4(f2tf32(in[2]), f2tf32(in[6]), f2tf32(in[3]), f2tf32(in[7]));
        return;
    }
    if (blk < NB_X + NB_WQT + NB_WPT) {
        __shared__ float ts[32][33];
        const float* src; float* dst; int N; int tq;
        if (blk < NB_X + NB_WQT) { src = wq; dst = g_wq; N = C3; tq = blk - NB_X; }
        else                     { src = wp; dst = g_wp; N = CC; tq = blk - NB_X - NB_WQT; }
        const int nTiles = N >> 5;
        const int k0 = (tq / nTiles) << 5;
        const int n0 = (tq % nTiles) << 5;
        #pragma unroll
        for (int j = 0; j < 4; j++) {
            int lin = tid + (j << 8);
            int r = lin >> 5, c = lin & 31;
            ts[r][c] = src[(size_t)(k0 + r) * N + n0 + c];
        }
        __syncthreads();
        #pragma unroll
        for (int j = 0; j < 4; j++) {
            int lin = tid + (j << 8);
            int r = lin >> 5, cpos = lin & 31;
            int klog = (cpos & ~7) | (((cpos & 1) << 2) | ((cpos & 7) >> 1));
            dst[(size_t)(n0 + r) * CC + k0 + cpos] = f2tf32(ts[klog][r]);
        }
        return;
    }
    int idx = (blk - (NB_X + NB_WQT + NB_WPT)) * 256 + tid;
    int t = idx >> 5, fi = idx & 31;
    double invf = exp(-(double)fi / 32.0 * 9.210340371976184);
    double da = (double)t * invf;
    g_cos[idx] = (float)cos(da);
    g_sin[idx] = (float)sin(da);
}

// ------------------------------------------------------------------
// TF32 GEMM (optional fused rope epilogue). Full-kt fragment preload:
// all 32 LDS.64 issued before the 64-mma block each k-tile.
// ------------------------------------------------------------------
#define STG 4
#define TSTR 24
#define GT_TILE (128*TSTR)

__global__ __launch_bounds__(128, 2) void gemm_pipe(
    const float* __restrict__ A, const float* __restrict__ Bt,
    float* __restrict__ C, int M, int N, int K, int fuse)
{
    extern __shared__ float sm[];
    float* As = sm;
    float* Bs = sm + STG * GT_TILE;

    const int tid  = threadIdx.x;
    const int lane = tid & 31;
    const int wid  = tid >> 5;
    const int wm   = (wid >> 1) << 6;
    const int wn   = (wid & 1) << 6;
    const int lq   = lane >> 2;
    const int lr   = lane & 3;
    const int row0 = blockIdx.y * 128;
    const int col0 = blockIdx.x * 128;

    const unsigned sA = smem_u32(As);
    const unsigned sB = smem_u32(Bs);
    const int KT = K >> 4;

    float acc[4][8][4];
    #pragma unroll
    for (int i = 0; i < 4; i++)
        #pragma unroll
        for (int j = 0; j < 8; j++)
            #pragma unroll
            for (int v = 0; v < 4; v++) acc[i][j][v] = 0.f;

    #define GEMM_ISSUE(kt, st) do {                                             \
        _Pragma("unroll")                                                        \
        for (int j_ = 0; j_ < 4; j_++) {                                         \
            int lin_ = tid + (j_ << 7);                                          \
            int r_ = lin_ >> 2, c_ = (lin_ & 3) << 2;                            \
            cp16(sA + (unsigned)((st)*GT_TILE + r_*TSTR + c_) * 4u,              \
                 A + (size_t)(row0 + r_) * K + ((kt) << 4) + c_);                \
            cp16(sB + (unsigned)((st)*GT_TILE + r_*TSTR + c_) * 4u,              \
                 Bt + (size_t)(col0 + r_) * K + ((kt) << 4) + c_);               \
        }                                                                        \
        CP_COMMIT();                                                             \
    } while (0)

    GEMM_ISSUE(0, 0);
    GEMM_ISSUE(1, 1);
    GEMM_ISSUE(2, 2);

    for (int kt = 0; kt < KT; kt++) {
        const int rem = KT - 1 - kt;
        if (rem >= 2)      CP_WAIT(2);
        else if (rem == 1) CP_WAIT(1);
        else               CP_WAIT(0);
        __syncthreads();
        if (kt + 3 < KT) GEMM_ISSUE(kt + 3, (kt + 3) & 3);

        const float* At = As + (kt & 3) * GT_TILE;
        const float* Bw = Bs + (kt & 3) * GT_TILE;

        // ---- preload ALL fragments for this k-tile (32 LDS.64) ----
        float2 aP0[2][4], aP1[2][4], bP[2][8];
        #pragma unroll
        for (int h = 0; h < 2; h++) {
            const int kp = (h << 3) + (lr << 1);
            #pragma unroll
            for (int mi = 0; mi < 4; mi++) {
                const int m = wm + (mi << 4) + lq;
                aP0[h][mi] = *(const float2*)(At + m * TSTR + kp);
                aP1[h][mi] = *(const float2*)(At + (m + 8) * TSTR + kp);
            }
            #pragma unroll
            for (int nj = 0; nj < 8; nj++) {
                const int n = wn + (nj << 3) + lq;
                bP[h][nj] = *(const float2*)(Bw + n * TSTR + kp);
            }
        }
        // ---- 64 mma, no interleaved loads ----
        #pragma unroll
        for (int h = 0; h < 2; h++)
            #pragma unroll
            for (int mi = 0; mi < 4; mi++)
                #pragma unroll
                for (int nj = 0; nj < 8; nj++)
                    mma_tf32(acc[mi][nj],
                             __float_as_uint(aP0[h][mi].x), __float_as_uint(aP1[h][mi].x),
                             __float_as_uint(aP0[h][mi].y), __float_as_uint(aP1[h][mi].y),
                             __float_as_uint(bP[h][nj].x),  __float_as_uint(bP[h][nj].y));
    }

    if (!fuse) {
        #pragma unroll
        for (int mi = 0; mi < 4; mi++) {
            const int r = row0 + wm + (mi << 4) + lq;
            #pragma unroll
            for (int nj = 0; nj < 8; nj++) {
                const int cc = col0 + wn + (nj << 3) + (lr << 1);
                *(float2*)(C + (size_t)r * N + cc)       = make_float2(acc[mi][nj][0], acc[mi][nj][1]);
                *(float2*)(C + (size_t)(r + 8) * N + cc) = make_float2(acc[mi][nj][2], acc[mi][nj][3]);
            }
        }
        return;
    }

    // ---- fused qkv epilogue: rope + split + permuted layouts ----
    const int seg  = col0 >> 10;
    const int hloc = ((col0 & 1023) + wn) >> 6;
    #pragma unroll
    for (int mi = 0; mi < 4; mi++) {
        #pragma unroll
        for (int half = 0; half < 2; half++) {
            const int m  = row0 + wm + (mi << 4) + lq + (half << 3);
            const int t  = m & 2047;
            const int bq = m >> 11;
            const int bh = bq * HH + hloc;
            const int tl = t & 7;
            const int tp = (t & ~7) | ((tl < 4) ? (tl << 1) : (((tl - 4) << 1) + 1));
            if (seg == 2) {
                #pragma unroll
                for (int nj = 0; nj < 8; nj++) {
                    #pragma unroll
                    for (int c = 0; c < 2; c++) {
                        const int d = (nj << 3) + (lr << 1) + c;
                        g_v[((size_t)bh * DD + d) * TT + tp] =
                            f2tf32(acc[mi][nj][(half << 1) + c]);
                    }
                }
            } else {
                #pragma unroll
                for (int nj = 0; nj < 4; nj++) {
                    #pragma unroll
                    for (int c = 0; c < 2; c++) {
                        const int jl   = (lr << 1) + c;
                        const int d_lo = (nj << 3) + jl;
                        const float a_lo = acc[mi][nj][(half << 1) + c];
                        const float a_hi = acc[mi][nj + 4][(half << 1) + c];
                        const float cs = g_cos[(t << 5) + d_lo];
                        const float sn = g_sin[(t << 5) + d_lo];
                        const float o_lo = a_lo * cs - a_hi * sn;
                        const float o_hi = a_hi * cs + a_lo * sn;
                        const int posl = (nj << 3) + p8(jl);
                        const int posh = ((nj + 4) << 3) + p8(jl);
                        if (seg == 0) {
                            const size_t ro = ((size_t)bh * TT + t) * DD;
                            g_q[ro + posl] = f2tf32(o_lo * QSC);
                            g_q[ro + posh] = f2tf32(o_hi * QSC);
                        } else {
                            const size_t ro = ((size_t)bh * TT + tp) * DD;
                            g_k[ro + posl] = f2tf32(o_lo);
                            g_k[ro + posh] = f2tf32(o_hi);
                        }
                    }
                }
            }
        }
    }
    #undef GEMM_ISSUE
}

// ------------------------------------------------------------------
// Flash attention (unchanged from R15)
// ------------------------------------------------------------------
#define KSTR 72
#define VSTR 72

__global__ __launch_bounds__(128, 3) void attn_pipe(
    const float* __restrict__ Q, const float* __restrict__ K,
    const float* __restrict__ V)
{
    extern __shared__ float sm[];
    float* Ks = sm;
    float* Vs = Ks + 2 * 64 * KSTR;

    const int tid  = threadIdx.x;
    const int lane = tid & 31;
    const int wid  = tid >> 5;
    const int wq   = wid << 4;
    const int lq   = lane >> 2;
    const int lr   = lane & 3;

    const int qt = gridDim.x - 1 - blockIdx.x;
    const int bh = blockIdx.y;
    const int q0 = qt << 6;
    const int b = bh >> 4, h = bh & 15;

    const float* Qb = Q + (size_t)bh * TT * DD;
    const float* Kb = K + (size_t)bh * TT * DD;
    const float* Vb = V + (size_t)bh * DD * TT;

    const unsigned sK = smem_u32(Ks);
    const unsigned sV = smem_u32(Vs);

    #define ATTN_ISSUE(kt, buf) do {                                           \
        const int k0_ = (kt) << 6;                                              \
        _Pragma("unroll")                                                       \
        for (int i_ = 0; i_ < 8; i_++) {                                        \
            int c_ = tid + (i_ << 7);                                           \
            int r_ = c_ >> 4, co_ = (c_ & 15) << 2;                             \
            cp16(sK + (unsigned)((buf)*64*KSTR + r_*KSTR + co_) * 4u,           \
                 Kb + (size_t)(k0_ + r_) * DD + co_);                           \
            cp16(sV + (unsigned)((buf)*64*VSTR + r_*VSTR + co_) * 4u,           \
                 Vb + (size_t)r_ * TT + k0_ + co_);                             \
        }                                                                       \
        CP_COMMIT();                                                            \
    } while (0)

    ATTN_ISSUE(0, 0);

    const int qrow = wq + lq;
    const float* Qr0 = Qb + (size_t)(q0 + qrow) * DD;
    const float* Qr8 = Qr0 + 8 * DD;
    unsigned qa[8][4];
    #pragma unroll
    for (int ks = 0; ks < 8; ks++) {
        const int pos = (ks << 3) + (lr << 1);
        float2 f0 = *(const float2*)(Qr0 + pos);
        float2 f8 = *(const float2*)(Qr8 + pos);
        qa[ks][0] = __float_as_uint(f0.x);
        qa[ks][1] = __float_as_uint(f8.x);
        qa[ks][2] = __float_as_uint(f0.y);
        qa[ks][3] = __float_as_uint(f8.y);
    }

    float l_lo = 0.f, l_hi = 0.f;
    float oc[8][4];
    #pragma unroll
    for (int nt = 0; nt < 8; nt++)
        #pragma unroll
        for (int v = 0; v < 4; v++) oc[nt][v] = 0.f;

    const int row_lo = wq + lq;
    const int row_hi = row_lo + 8;

    for (int kt = 0; kt <= qt; kt++) {
        CP_WAIT(0);
        __syncthreads();
        if (kt < qt) ATTN_ISSUE(kt + 1, (kt + 1) & 1);

        const float* Kt = Ks + (kt & 1) * 64 * KSTR;
        const float* Vt = Vs + (kt & 1) * 64 * VSTR;

        float sc[8][4];
        #pragma unroll
        for (int nt = 0; nt < 8; nt++)
            #pragma unroll
            for (int v = 0; v < 4; v++) sc[nt][v] = 0.f;

        #pragma unroll
        for (int ks = 0; ks < 8; ks++) {
            const int pos = (ks << 3) + (lr << 1);
            #pragma unroll
            for (int nt = 0; nt < 8; nt++) {
                const int key = (nt << 3) + lq;
                float2 kf = *(const float2*)(Kt + key * KSTR + pos);
                mma_tf32(sc[nt], qa[ks][0], qa[ks][1], qa[ks][2], qa[ks][3],
                         __float_as_uint(kf.x), __float_as_uint(kf.y));
            }
        }

        if (kt == qt) {
            #pragma unroll
            for (int nt = 0; nt < 8; nt++) {
                const int k0c = (nt << 3) + lr;
                const int k1c = k0c + 4;
                sc[nt][0] = (k0c <= row_lo) ? sc[nt][0] : -INFINITY;
                sc[nt][1] = (k1c <= row_lo) ? sc[nt][1] : -INFINITY;
                sc[nt][2] = (k0c <= row_hi) ? sc[nt][2] : -INFINITY;
                sc[nt][3] = (k1c <= row_hi) ? sc[nt][3] : -INFINITY;
            }
        }

        #pragma unroll
        for (int nt = 0; nt < 8; nt++) {
            sc[nt][0] = ex2(sc[nt][0]);
            sc[nt][1] = ex2(sc[nt][1]);
            sc[nt][2] = ex2(sc[nt][2]);
            sc[nt][3] = ex2(sc[nt][3]);
            l_lo += sc[nt][0] + sc[nt][1];
            l_hi += sc[nt][2] + sc[nt][3];
        }

        #pragma unroll
        for (int ks = 0; ks < 8; ks++) {
            unsigned a0 = __float_as_uint(f2tf32(sc[ks][0]));
            unsigned a1 = __float_as_uint(f2tf32(sc[ks][2]));
            unsigned a2 = __float_as_uint(f2tf32(sc[ks][1]));
            unsigned a3 = __float_as_uint(f2tf32(sc[ks][3]));

            const int pos = (ks << 3) + (lr << 1);
            #pragma unroll
            for (int nt = 0; nt < 8; nt++) {
                const int dd = (nt << 3) + lq;
                float2 vf = *(const float2*)(Vt + dd * VSTR + pos);
                mma_tf32(oc[nt], a0, a1, a2, a3,
                         __float_as_uint(vf.x), __float_as_uint(vf.y));
            }
        }
    }

    l_lo += __shfl_xor_sync(0xffffffffu, l_lo, 1);
    l_lo += __shfl_xor_sync(0xffffffffu, l_lo, 2);
    l_hi += __shfl_xor_sync(0xffffffffu, l_hi, 1);
    l_hi += __shfl_xor_sync(0xffffffffu, l_hi, 2);
    const float inv_lo = 1.f / l_lo;
    const float inv_hi = 1.f / l_hi;
    const int t_lo = q0 + qrow;
    float* out_lo = g_y + ((size_t)(b * TT + t_lo)) * CC + h * DD;
    float* out_hi = g_y + ((size_t)(b * TT + t_lo + 8)) * CC + h * DD;
    const int j0 = lr << 1, j1 = j0 + 1;
    const int p0 = ((j0 & 3) << 1) | (j0 >> 2);
    const int p1 = ((j1 & 3) << 1) | (j1 >> 2);
    #pragma unroll
    for (int nt = 0; nt < 8; nt++) {
        const int cb = nt << 3;
        out_lo[cb + p0] = f2tf32(oc[nt][0] * inv_lo);
        out_lo[cb + p1] = f2tf32(oc[nt][1] * inv_lo);
        out_hi[cb + p0] = f2tf32(oc[nt][2] * inv_hi);
        out_hi[cb + p1] = f2tf32(oc[nt][3] * inv_hi);
    }
    #undef ATTN_ISSUE
}

// ------------------------------------------------------------------
// Launch: prep, qkv(fused rope), attention, proj
// ------------------------------------------------------------------
extern "C" void kernel_launch(void* const* d_in, const int* in_sizes, int n_in,
                              void* d_out, int out_size)
{
    const float* x      = (const float*)d_in[0];
    const float* w_qkv  = (const float*)d_in[1];
    const float* w_proj = (const float*)d_in[2];
    float* out = (float*)d_out;

    float *p_q, *p_k, *p_v, *p_y, *p_xt, *p_wq, *p_wp;
    cudaGetSymbolAddress((void**)&p_q, g_q);
    cudaGetSymbolAddress((void**)&p_k, g_k);
    cudaGetSymbolAddress((void**)&p_v, g_v);
    cudaGetSymbolAddress((void**)&p_y, g_y);
    cudaGetSymbolAddress((void**)&p_xt, g_xt);
    cudaGetSymbolAddress((void**)&p_wq, g_wq);
    cudaGetSymbolAddress((void**)&p_wp, g_wp);

    // 1. prep
    prep_kernel<<<NB_PREP, 256>>>(x, w_qkv, w_proj);

    const int gemm_smem = STG * 2 * GT_TILE * (int)sizeof(float);  // 98304
    cudaFuncSetAttribute(gemm_pipe,
                         cudaFuncAttributeMaxDynamicSharedMemorySize, gemm_smem);

    // 2. qkv GEMM with fused rope/split epilogue
    {
        dim3 grid(C3 / 128, MM / 128);
        gemm_pipe<<<grid, 128, gemm_smem>>>(p_xt, p_wq, p_y /*unused*/, MM, C3, CC, 1);
    }

    // 3. attention
    {
        const int smem = (2*64*KSTR + 2*64*VSTR) * (int)sizeof(float); // 73728
        cudaFuncSetAttribute(attn_pipe,
                             cudaFuncAttributeMaxDynamicSharedMemorySize, smem);
        dim3 grid(TT / 64, BB * HH);
        attn_pipe<<<grid, 128, smem>>>(p_q, p_k, p_v);
    }

    // 4. out = y @ wp^T
    {
        dim3 grid(CC / 128, MM / 128);
        gemm_pipe<<<grid, 128, gemm_smem>>>(p_y, p_wp, out, MM, CC, CC, 0);
    }
}